// round 1
// baseline (speedup 1.0000x reference)
#include <cuda_runtime.h>
#include <math.h>

#define N_NODES 100000
#define F_DIM   128
#define DEG     5
#define N_EDGES (N_NODES * DEG)
#define MIN_NORM 1e-15f
#define MAXNORM  0.996f   // (1 - 4e-3)/sqrt(c), c=1

// ---------------- scratch (device globals; no allocations allowed) ----------
__device__ __align__(16) float g_mxT[(size_t)N_NODES * F_DIM];   // x @ W^T, [N,F]
__device__ __align__(16) float g_u[N_NODES];
__device__ __align__(16) float g_v[N_NODES];
__device__ int   g_cnt[N_NODES];                                  // in-degree of dst
__device__ __align__(16) float g_msq[F_DIM];                      // sum_n mx[n,f]^2
__device__ __align__(16) float g_wsq[F_DIM];                      // sum_n cnt[n]*mx[n,f]^2
__device__ __align__(16) float g_alpha[F_DIM];
__device__ __align__(16) float g_c1[F_DIM];
__device__ __align__(16) float g_c2[F_DIM];
__device__ float g_sumsqE;
__device__ float g_anorm;

// ---------------- math helpers ----------------------------------------------
__device__ __forceinline__ float clip1(float x) {
    return fminf(fmaxf(x, -1.0f + 1e-7f), 1.0f - 1e-7f);
}
__device__ __forceinline__ float artanh_c(float x) { return atanhf(clip1(x)); }

// chain: s = mobius factor; then proj; then logmap0. returns total scale factor.
__device__ __forceinline__ float proj_logmap0_factor(float s, float mn) {
    float r  = fabsf(s) * mn;                       // norm after mobius res
    float pf = (r > MAXNORM) ? (MAXNORM / r) : 1.0f;
    float pn = fmaxf(r * pf, MIN_NORM);             // norm after proj
    return s * pf * artanh_c(pn) / pn;              // * logmap0 factor
}
// expmap0 then proj: scale factor for a row with norm un
__device__ __forceinline__ float expmap0_proj_factor(float un) {
    un = fmaxf(un, MIN_NORM);
    float g  = tanhf(un) / un;
    float r  = fabsf(g) * un;                       // = tanh(un)
    float pf = (r > MAXNORM) ? (MAXNORM / r) : 1.0f;
    return g * pf;
}

__device__ __forceinline__ void fma4(float4& a, float s, const float4& w) {
    a.x += s * w.x; a.y += s * w.y; a.z += s * w.z; a.w += s * w.w;
}

// ---------------- K0: zero accumulators --------------------------------------
__global__ void k_zero() {
    int i = blockIdx.x * blockDim.x + threadIdx.x;
    if (i < N_NODES) g_cnt[i] = 0;
    if (i < F_DIM) { g_msq[i] = 0.0f; g_wsq[i] = 0.0f; }
    if (i == 0) g_sumsqE = 0.0f;
}

// ---------------- K0b: in-degree histogram of dst -----------------------------
__global__ void k_hist(const int* __restrict__ dst) {
    int e = blockIdx.x * blockDim.x + threadIdx.x;
    if (e < N_EDGES) atomicAdd(&g_cnt[dst[e]], 1);
}

// ---------------- K1: GEMM mxT = x @ W^T with fused column reductions --------
#define WS_LD 132   // padded lead dim for W^T in smem (4-way store conflicts only)
#define XS_LD 72    // padded lead dim for x tile transposed
#define GEMM_SMEM ((128 * WS_LD + 128 * XS_LD) * 4)

__global__ __launch_bounds__(256) void k_gemm(const float* __restrict__ x,
                                              const float* __restrict__ W) {
    extern __shared__ float sh[];
    float* Ws  = sh;                  // Ws[k*WS_LD + f] = W[f,k]
    float* xsT = sh + 128 * WS_LD;    // xsT[k*XS_LD + r] = x[base+r, k]
    const int tid  = threadIdx.x;
    const int base = blockIdx.x * 64;

    for (int i = tid; i < 128 * 128; i += 256) {
        int f = i >> 7, k = i & 127;
        Ws[k * WS_LD + f] = W[i];
    }
    for (int i = tid; i < 64 * 128; i += 256) {
        int r = i >> 7, k = i & 127;
        int row = base + r;
        xsT[k * XS_LD + r] = (row < N_NODES) ? x[(size_t)row * 128 + k] : 0.0f;
    }
    __syncthreads();

    const int cg = tid & 31;    // column group: 4 cols
    const int rg = tid >> 5;    // row group: 8 rows
    float4 acc[8];
#pragma unroll
    for (int r = 0; r < 8; r++) acc[r] = make_float4(0.f, 0.f, 0.f, 0.f);

#pragma unroll 4
    for (int k = 0; k < 128; k++) {
        float4 wv = *(const float4*)&Ws[k * WS_LD + cg * 4];
        float4 xa = *(const float4*)&xsT[k * XS_LD + rg * 8];
        float4 xb = *(const float4*)&xsT[k * XS_LD + rg * 8 + 4];
        fma4(acc[0], xa.x, wv); fma4(acc[1], xa.y, wv);
        fma4(acc[2], xa.z, wv); fma4(acc[3], xa.w, wv);
        fma4(acc[4], xb.x, wv); fma4(acc[5], xb.y, wv);
        fma4(acc[6], xb.z, wv); fma4(acc[7], xb.w, wv);
    }

    // write tile + local column sums of squares (plain / indegree-weighted)
    float ssq[4] = {0, 0, 0, 0}, wsl[4] = {0, 0, 0, 0};
#pragma unroll
    for (int r = 0; r < 8; r++) {
        int row = base + rg * 8 + r;
        if (row < N_NODES) {
            *(float4*)&g_mxT[(size_t)row * 128 + cg * 4] = acc[r];
            float cf = (float)g_cnt[row];
            float vx = acc[r].x, vy = acc[r].y, vz = acc[r].z, vw = acc[r].w;
            ssq[0] += vx * vx; ssq[1] += vy * vy; ssq[2] += vz * vz; ssq[3] += vw * vw;
            wsl[0] += cf * vx * vx; wsl[1] += cf * vy * vy;
            wsl[2] += cf * vz * vz; wsl[3] += cf * vw * vw;
        }
    }
    __syncthreads();   // xsT no longer needed; reuse as reduction buffer
    float* redA = xsT;
    float* redB = xsT + 1024;
#pragma unroll
    for (int j = 0; j < 4; j++) {
        redA[rg * 128 + cg * 4 + j] = ssq[j];
        redB[rg * 128 + cg * 4 + j] = wsl[j];
    }
    __syncthreads();
    if (tid < 128) {
        float s = 0.f, w = 0.f;
#pragma unroll
        for (int g = 0; g < 8; g++) { s += redA[g * 128 + tid]; w += redB[g * 128 + tid]; }
        atomicAdd(&g_msq[tid], s);
        atomicAdd(&g_wsq[tid], w);
    }
}

// ---------------- K2: per-feature scalar chain --------------------------------
__global__ __launch_bounds__(256) void k_scalars(const float* __restrict__ W,
                                                 const float* __restrict__ a) {
    __shared__ float sred[256];
    int tid = threadIdx.x;
    float av = a[tid];
    sred[tid] = av * av;
    __syncthreads();
    for (int s = 128; s > 0; s >>= 1) {
        if (tid < s) sred[tid] += sred[tid + s];
        __syncthreads();
    }
    float an = fmaxf(sqrtf(sred[0]), MIN_NORM);
    if (tid == 0) g_anorm = an;

    if (tid < 128) {
        int f = tid;
        float xs2 = 0.0f;
        for (int k = 0; k < 128; k++) { float w = W[f * 128 + k]; xs2 += w * w; }
        float xn = fmaxf(sqrtf(xs2), MIN_NORM);
        float mn = fmaxf(sqrtf(g_msq[f]), MIN_NORM);
        // mobius_matvec row factor, then proj, then logmap0
        float s1 = tanhf(mn / xn * artanh_c(xn)) / mn;
        float alpha = proj_logmap0_factor(s1, mn);
        g_alpha[f] = alpha;
        // edge_h = proj(expmap0(...)) row factors (src rows / dst rows)
        float un_s = fabsf(alpha) * sqrtf(5.0f * g_msq[f]);
        float un_d = fabsf(alpha) * sqrtf(g_wsq[f]);
        float beta_s = expmap0_proj_factor(un_s);
        float beta_d = expmap0_proj_factor(un_d);
        g_c1[f] = a[f]       * beta_s * alpha;
        g_c2[f] = a[128 + f] * beta_d * alpha;
    }
}

// ---------------- K3: u[n] = c1 . mxT[n], v[n] = c2 . mxT[n] ------------------
__global__ void k_uv() {
    int gw   = (blockIdx.x * blockDim.x + threadIdx.x) >> 5;
    int lane = threadIdx.x & 31;
    if (gw >= N_NODES) return;
    float4 c1 = *(const float4*)&g_c1[lane * 4];
    float4 c2 = *(const float4*)&g_c2[lane * 4];
    float4 m  = *(const float4*)&g_mxT[(size_t)gw * 128 + lane * 4];
    float du = m.x * c1.x + m.y * c1.y + m.z * c1.z + m.w * c1.w;
    float dv = m.x * c2.x + m.y * c2.y + m.z * c2.z + m.w * c2.w;
#pragma unroll
    for (int o = 16; o > 0; o >>= 1) {
        du += __shfl_xor_sync(0xffffffffu, du, o);
        dv += __shfl_xor_sync(0xffffffffu, dv, o);
    }
    if (lane == 0) { g_u[gw] = du; g_v[gw] = dv; }
}

// ---------------- K4: sum of squares of edge logits ---------------------------
__global__ void k_sumsq(const int* __restrict__ src, const int* __restrict__ dst) {
    __shared__ float sb[256];
    int e = blockIdx.x * blockDim.x + threadIdx.x;
    float sq = 0.0f;
    if (e < N_EDGES) {
        float m = g_u[src[e]] + g_v[dst[e]];
        sq = m * m;
    }
    sb[threadIdx.x] = sq;
    __syncthreads();
    for (int s = 128; s > 0; s >>= 1) {
        if (threadIdx.x < s) sb[threadIdx.x] += sb[threadIdx.x + s];
        __syncthreads();
    }
    if (threadIdx.x == 0) atomicAdd(&g_sumsqE, sb[0]);
}

// ---------------- K5: final aggregation + output transform (warp per node) ----
__device__ __forceinline__ float compute_gamma() {
    float mn = fmaxf(sqrtf(g_sumsqE), MIN_NORM);
    float an = g_anorm;
    float s2 = tanhf(mn / an * artanh_c(an)) / mn;
    return proj_logmap0_factor(s2, mn);
}

__global__ __launch_bounds__(256) void k_final(const int* __restrict__ src,
                                               const int* __restrict__ dst,
                                               float* __restrict__ out) {
    int n    = (blockIdx.x * blockDim.x + threadIdx.x) >> 5;
    int lane = threadIdx.x & 31;
    if (n >= N_NODES) return;
    float gamma = compute_gamma();

    float wj = 0.0f;
    int   dj = 0;
    if (lane < DEG) {
        int e = n * DEG + lane;
        int s = src[e];
        dj = dst[e];
        float mxE = g_u[s] + g_v[dj];
        float ee  = gamma * mxE;
        float ge  = 0.5f * ee * (1.0f + erff(ee * 0.70710678118654752f));  // exact gelu
        wj = expf(-ge);
    }

    float4 acc = make_float4(0.f, 0.f, 0.f, 0.f);
    float wsum = 0.0f;
#pragma unroll
    for (int j = 0; j < DEG; j++) {
        float w = __shfl_sync(0xffffffffu, wj, j);
        int   d = __shfl_sync(0xffffffffu, dj, j);
        float4 m = *(const float4*)&g_mxT[(size_t)d * 128 + lane * 4];
        acc.x += w * m.x; acc.y += w * m.y; acc.z += w * m.z; acc.w += w * m.w;
        wsum += w;
    }
    float4 al  = *(const float4*)&g_alpha[lane * 4];
    float  inv = 1.0f / wsum;
    float4 hp = make_float4(acc.x * al.x * inv, acc.y * al.y * inv,
                            acc.z * al.z * inv, acc.w * al.w * inv);
    // elu
    float4 e4;
    e4.x = (hp.x > 0.f) ? hp.x : expm1f(hp.x);
    e4.y = (hp.y > 0.f) ? hp.y : expm1f(hp.y);
    e4.z = (hp.z > 0.f) ? hp.z : expm1f(hp.z);
    e4.w = (hp.w > 0.f) ? hp.w : expm1f(hp.w);
    float ssq = e4.x * e4.x + e4.y * e4.y + e4.z * e4.z + e4.w * e4.w;
#pragma unroll
    for (int o = 16; o > 0; o >>= 1) ssq += __shfl_xor_sync(0xffffffffu, ssq, o);
    float un  = fmaxf(sqrtf(ssq), MIN_NORM);
    float fac = expmap0_proj_factor(un);
    float4 o4 = make_float4(e4.x * fac, e4.y * fac, e4.z * fac, e4.w * fac);
    *(float4*)&out[(size_t)n * 128 + lane * 4] = o4;
}

// ---------------- launch ------------------------------------------------------
extern "C" void kernel_launch(void* const* d_in, const int* in_sizes, int n_in,
                              void* d_out, int out_size) {
    const float* x = nullptr;
    const float* W = nullptr;
    const float* a = nullptr;
    const int* edge = nullptr;
    for (int i = 0; i < n_in; i++) {
        switch (in_sizes[i]) {
            case N_NODES * F_DIM: x    = (const float*)d_in[i]; break;
            case 2 * N_EDGES:     edge = (const int*)d_in[i];   break;
            case F_DIM * F_DIM:   W    = (const float*)d_in[i]; break;
            case 2 * F_DIM:       a    = (const float*)d_in[i]; break;
            default: break;
        }
    }
    const int* src = edge;
    const int* dst = edge + N_EDGES;
    float* out = (float*)d_out;

    cudaFuncSetAttribute(k_gemm, cudaFuncAttributeMaxDynamicSharedMemorySize, GEMM_SMEM);

    k_zero<<<(N_NODES + 255) / 256, 256>>>();
    k_hist<<<(N_EDGES + 255) / 256, 256>>>(dst);
    k_gemm<<<(N_NODES + 63) / 64, 256, GEMM_SMEM>>>(x, W);
    k_scalars<<<1, 256>>>(W, a);
    {
        long long thr = (long long)N_NODES * 32;
        k_uv<<<(unsigned)((thr + 255) / 256), 256>>>();
    }
    k_sumsq<<<(N_EDGES + 255) / 256, 256>>>(src, dst);
    {
        long long thr = (long long)N_NODES * 32;
        k_final<<<(unsigned)((thr + 255) / 256), 256>>>(src, dst, out);
    }
    (void)out_size;
}

// round 2
// speedup vs baseline: 1.0587x; 1.0587x over previous
#include <cuda_runtime.h>
#include <math.h>

#define N_NODES 100000
#define F_DIM   128
#define DEG     5
#define N_EDGES (N_NODES * DEG)
#define MIN_NORM 1e-15f
#define MAXNORM  0.996f   // (1 - 4e-3)/sqrt(c), c=1

// ---------------- scratch (device globals; no allocations allowed) ----------
__device__ __align__(16) float g_mxT[(size_t)N_NODES * F_DIM];   // x @ W^T, [N,F]
__device__ __align__(16) float g_u[N_NODES];
__device__ __align__(16) float g_v[N_NODES];
__device__ int   g_cnt[N_NODES];                                  // in-degree of dst
__device__ __align__(16) float g_msq[F_DIM];                      // sum_n mx[n,f]^2
__device__ __align__(16) float g_wsq[F_DIM];                      // sum_n cnt[n]*mx[n,f]^2
__device__ __align__(16) float g_xs2[F_DIM];                      // ||W[f,:]||^2
__device__ __align__(16) float g_alpha[F_DIM];
__device__ __align__(16) float g_c1[F_DIM];
__device__ __align__(16) float g_c2[F_DIM];
__device__ float g_sumsqE;
__device__ float g_anorm;

// ---------------- math helpers ----------------------------------------------
__device__ __forceinline__ float clip1(float x) {
    return fminf(fmaxf(x, -1.0f + 1e-7f), 1.0f - 1e-7f);
}
__device__ __forceinline__ float artanh_c(float x) { return atanhf(clip1(x)); }

__device__ __forceinline__ float proj_logmap0_factor(float s, float mn) {
    float r  = fabsf(s) * mn;
    float pf = (r > MAXNORM) ? (MAXNORM / r) : 1.0f;
    float pn = fmaxf(r * pf, MIN_NORM);
    return s * pf * artanh_c(pn) / pn;
}
__device__ __forceinline__ float expmap0_proj_factor(float un) {
    un = fmaxf(un, MIN_NORM);
    float g  = tanhf(un) / un;
    float r  = fabsf(g) * un;
    float pf = (r > MAXNORM) ? (MAXNORM / r) : 1.0f;
    return g * pf;
}

#define FMA2(d, a, b) asm("fma.rn.f32x2 %0, %1, %2, %0;" : "+l"(d) : "l"(a), "l"(b))

// ---------------- K0: zero accumulators --------------------------------------
__global__ void k_zero() {
    int i = blockIdx.x * blockDim.x + threadIdx.x;
    if (i < N_NODES) g_cnt[i] = 0;
    if (i < F_DIM) { g_msq[i] = 0.0f; g_wsq[i] = 0.0f; }
    if (i == 0) g_sumsqE = 0.0f;
}

// ---------------- K0b: in-degree histogram of dst -----------------------------
__global__ void k_hist(const int* __restrict__ dst) {
    int e = blockIdx.x * blockDim.x + threadIdx.x;
    if (e < N_EDGES) atomicAdd(&g_cnt[dst[e]], 1);
}

// ---------------- K0c: W row norms (one warp per feature row) -----------------
__global__ void k_wnorm(const float* __restrict__ W) {
    int w    = (blockIdx.x * blockDim.x + threadIdx.x) >> 5;
    int lane = threadIdx.x & 31;
    if (w >= F_DIM) return;
    float4 v = *(const float4*)&W[w * 128 + lane * 4];
    float s = v.x * v.x + v.y * v.y + v.z * v.z + v.w * v.w;
#pragma unroll
    for (int o = 16; o > 0; o >>= 1) s += __shfl_xor_sync(0xffffffffu, s, o);
    if (lane == 0) g_xs2[w] = s;
}

// ---------------- K1: FFMA2 GEMM mxT = x @ W^T + fused column reductions ------
#define KC     64
#define WS_LD  132    // [KC][WS_LD]: Ws[k][f] = W[f][kc+k]
#define XD_LD  268    // [KC][XD_LD]: xd[k][2r..2r+1] = {x[base+r][kc+k]} duplicated
#define GEMM_SMEM ((KC * WS_LD + KC * XD_LD) * 4)

__global__ __launch_bounds__(256, 2) void k_gemm(const float* __restrict__ x,
                                                 const float* __restrict__ W) {
    extern __shared__ __align__(16) float sh[];
    float* Ws = sh;                 // KC*WS_LD
    float* xd = sh + KC * WS_LD;    // KC*XD_LD
    const int tid  = threadIdx.x;
    const int base = blockIdx.x * 128;
    const int cg   = tid & 15;      // 8 cols: cg*8 .. cg*8+7
    const int rg   = tid >> 4;      // 8 rows: rg*8 .. rg*8+7

    unsigned long long acc[8][4];
#pragma unroll
    for (int r = 0; r < 8; r++)
#pragma unroll
        for (int c = 0; c < 4; c++) acc[r][c] = 0ull;   // {0.f, 0.f}

    for (int kc = 0; kc < 128; kc += KC) {
        __syncthreads();
        // stage W chunk: Ws[kk][f]
        for (int i = tid; i < 128 * KC; i += 256) {
            int f = i >> 6, kk = i & (KC - 1);
            Ws[kk * WS_LD + f] = W[f * 128 + kc + kk];
        }
        // stage x chunk duplicated: xd[kk][2r],[2r+1] = x[base+r][kc+kk]
        for (int i = tid; i < 128 * KC; i += 256) {
            int r = i >> 6, kk = i & (KC - 1);
            int row = base + r;
            float v = (row < N_NODES) ? x[(size_t)row * 128 + kc + kk] : 0.0f;
            *(float2*)&xd[kk * XD_LD + 2 * r] = make_float2(v, v);
        }
        __syncthreads();

#pragma unroll 8
        for (int k = 0; k < KC; k++) {
            ulonglong2 wA = *(const ulonglong2*)&Ws[k * WS_LD + cg * 8];
            ulonglong2 wB = *(const ulonglong2*)&Ws[k * WS_LD + cg * 8 + 4];
            ulonglong2 x0 = *(const ulonglong2*)&xd[k * XD_LD + rg * 16];
            ulonglong2 x1 = *(const ulonglong2*)&xd[k * XD_LD + rg * 16 + 4];
            ulonglong2 x2 = *(const ulonglong2*)&xd[k * XD_LD + rg * 16 + 8];
            ulonglong2 x3 = *(const ulonglong2*)&xd[k * XD_LD + rg * 16 + 12];
            unsigned long long wp[4] = {wA.x, wA.y, wB.x, wB.y};
            unsigned long long xp[8] = {x0.x, x0.y, x1.x, x1.y, x2.x, x2.y, x3.x, x3.y};
#pragma unroll
            for (int r = 0; r < 8; r++) {
#pragma unroll
                for (int c = 0; c < 4; c++) FMA2(acc[r][c], xp[r], wp[c]);
            }
        }
    }

    // epilogue: store tile + per-feature sum-of-squares (plain / degree-weighted)
    float ssq[8], wsl[8];
#pragma unroll
    for (int j = 0; j < 8; j++) { ssq[j] = 0.f; wsl[j] = 0.f; }

#pragma unroll
    for (int r = 0; r < 8; r++) {
        int row = base + rg * 8 + r;
        if (row < N_NODES) {
            float2 p0 = *(float2*)&acc[r][0];
            float2 p1 = *(float2*)&acc[r][1];
            float2 p2 = *(float2*)&acc[r][2];
            float2 p3 = *(float2*)&acc[r][3];
            *(float4*)&g_mxT[(size_t)row * 128 + cg * 8]     = make_float4(p0.x, p0.y, p1.x, p1.y);
            *(float4*)&g_mxT[(size_t)row * 128 + cg * 8 + 4] = make_float4(p2.x, p2.y, p3.x, p3.y);
            float cf = (float)g_cnt[row];
            float vj[8] = {p0.x, p0.y, p1.x, p1.y, p2.x, p2.y, p3.x, p3.y};
#pragma unroll
            for (int j = 0; j < 8; j++) {
                float sq = vj[j] * vj[j];
                ssq[j] += sq;
                wsl[j] += cf * sq;
            }
        }
    }
    __syncthreads();                 // smem reuse for reduction
    float* redA = sh;                // [16][128]
    float* redB = sh + 2048;         // [16][128]
#pragma unroll
    for (int j = 0; j < 8; j++) {
        redA[rg * 128 + cg * 8 + j] = ssq[j];
        redB[rg * 128 + cg * 8 + j] = wsl[j];
    }
    __syncthreads();
    if (tid < 128) {
        float s = 0.f, w = 0.f;
#pragma unroll
        for (int g = 0; g < 16; g++) { s += redA[g * 128 + tid]; w += redB[g * 128 + tid]; }
        atomicAdd(&g_msq[tid], s);
        atomicAdd(&g_wsq[tid], w);
    }
}

// ---------------- K2: per-feature scalar chain (cheap now) --------------------
__global__ __launch_bounds__(256) void k_scalars(const float* __restrict__ a) {
    __shared__ float sred[256];
    int tid = threadIdx.x;
    float av = a[tid];
    sred[tid] = av * av;
    __syncthreads();
    for (int s = 128; s > 0; s >>= 1) {
        if (tid < s) sred[tid] += sred[tid + s];
        __syncthreads();
    }
    float an = fmaxf(sqrtf(sred[0]), MIN_NORM);
    if (tid == 0) g_anorm = an;

    if (tid < 128) {
        int f = tid;
        float xn = fmaxf(sqrtf(g_xs2[f]), MIN_NORM);
        float mn = fmaxf(sqrtf(g_msq[f]), MIN_NORM);
        float s1 = tanhf(mn / xn * artanh_c(xn)) / mn;
        float alpha = proj_logmap0_factor(s1, mn);
        g_alpha[f] = alpha;
        float un_s = fabsf(alpha) * sqrtf(5.0f * g_msq[f]);
        float un_d = fabsf(alpha) * sqrtf(g_wsq[f]);
        g_c1[f] = a[f]       * expmap0_proj_factor(un_s) * alpha;
        g_c2[f] = a[128 + f] * expmap0_proj_factor(un_d) * alpha;
    }
}

// ---------------- K3: u[n] = c1 . mxT[n], v[n] = c2 . mxT[n] ------------------
__global__ void k_uv() {
    int gw   = (blockIdx.x * blockDim.x + threadIdx.x) >> 5;
    int lane = threadIdx.x & 31;
    if (gw >= N_NODES) return;
    float4 c1 = *(const float4*)&g_c1[lane * 4];
    float4 c2 = *(const float4*)&g_c2[lane * 4];
    float4 m  = *(const float4*)&g_mxT[(size_t)gw * 128 + lane * 4];
    float du = m.x * c1.x + m.y * c1.y + m.z * c1.z + m.w * c1.w;
    float dv = m.x * c2.x + m.y * c2.y + m.z * c2.z + m.w * c2.w;
#pragma unroll
    for (int o = 16; o > 0; o >>= 1) {
        du += __shfl_xor_sync(0xffffffffu, du, o);
        dv += __shfl_xor_sync(0xffffffffu, dv, o);
    }
    if (lane == 0) { g_u[gw] = du; g_v[gw] = dv; }
}

// ---------------- K4: sum of squares of edge logits ---------------------------
__global__ void k_sumsq(const int* __restrict__ src, const int* __restrict__ dst) {
    __shared__ float sb[256];
    int e = blockIdx.x * blockDim.x + threadIdx.x;
    float sq = 0.0f;
    if (e < N_EDGES) {
        float m = g_u[src[e]] + g_v[dst[e]];
        sq = m * m;
    }
    sb[threadIdx.x] = sq;
    __syncthreads();
    for (int s = 128; s > 0; s >>= 1) {
        if (threadIdx.x < s) sb[threadIdx.x] += sb[threadIdx.x + s];
        __syncthreads();
    }
    if (threadIdx.x == 0) atomicAdd(&g_sumsqE, sb[0]);
}

// ---------------- K5: final aggregation + output transform (warp per node) ----
__device__ __forceinline__ float compute_gamma() {
    float mn = fmaxf(sqrtf(g_sumsqE), MIN_NORM);
    float an = g_anorm;
    float s2 = tanhf(mn / an * artanh_c(an)) / mn;
    return proj_logmap0_factor(s2, mn);
}

__global__ __launch_bounds__(256) void k_final(const int* __restrict__ src,
                                               const int* __restrict__ dst,
                                               float* __restrict__ out) {
    int n    = (blockIdx.x * blockDim.x + threadIdx.x) >> 5;
    int lane = threadIdx.x & 31;
    if (n >= N_NODES) return;
    float gamma = compute_gamma();

    float wj = 0.0f;
    int   dj = 0;
    if (lane < DEG) {
        int e = n * DEG + lane;
        int s = src[e];
        dj = dst[e];
        float mxE = g_u[s] + g_v[dj];
        float ee  = gamma * mxE;
        float ge  = 0.5f * ee * (1.0f + erff(ee * 0.70710678118654752f));
        wj = expf(-ge);
    }

    float4 acc = make_float4(0.f, 0.f, 0.f, 0.f);
    float wsum = 0.0f;
#pragma unroll
    for (int j = 0; j < DEG; j++) {
        float w = __shfl_sync(0xffffffffu, wj, j);
        int   d = __shfl_sync(0xffffffffu, dj, j);
        float4 m = *(const float4*)&g_mxT[(size_t)d * 128 + lane * 4];
        acc.x += w * m.x; acc.y += w * m.y; acc.z += w * m.z; acc.w += w * m.w;
        wsum += w;
    }
    float4 al  = *(const float4*)&g_alpha[lane * 4];
    float  inv = 1.0f / wsum;
    float4 hp = make_float4(acc.x * al.x * inv, acc.y * al.y * inv,
                            acc.z * al.z * inv, acc.w * al.w * inv);
    float4 e4;
    e4.x = (hp.x > 0.f) ? hp.x : expm1f(hp.x);
    e4.y = (hp.y > 0.f) ? hp.y : expm1f(hp.y);
    e4.z = (hp.z > 0.f) ? hp.z : expm1f(hp.z);
    e4.w = (hp.w > 0.f) ? hp.w : expm1f(hp.w);
    float ssq = e4.x * e4.x + e4.y * e4.y + e4.z * e4.z + e4.w * e4.w;
#pragma unroll
    for (int o = 16; o > 0; o >>= 1) ssq += __shfl_xor_sync(0xffffffffu, ssq, o);
    float un  = fmaxf(sqrtf(ssq), MIN_NORM);
    float fac = expmap0_proj_factor(un);
    float4 o4 = make_float4(e4.x * fac, e4.y * fac, e4.z * fac, e4.w * fac);
    *(float4*)&out[(size_t)n * 128 + lane * 4] = o4;
}

// ---------------- launch ------------------------------------------------------
extern "C" void kernel_launch(void* const* d_in, const int* in_sizes, int n_in,
                              void* d_out, int out_size) {
    const float* x = nullptr;
    const float* W = nullptr;
    const float* a = nullptr;
    const int* edge = nullptr;
    for (int i = 0; i < n_in; i++) {
        switch (in_sizes[i]) {
            case N_NODES * F_DIM: x    = (const float*)d_in[i]; break;
            case 2 * N_EDGES:     edge = (const int*)d_in[i];   break;
            case F_DIM * F_DIM:   W    = (const float*)d_in[i]; break;
            case 2 * F_DIM:       a    = (const float*)d_in[i]; break;
            default: break;
        }
    }
    const int* src = edge;
    const int* dst = edge + N_EDGES;
    float* out = (float*)d_out;

    cudaFuncSetAttribute(k_gemm, cudaFuncAttributeMaxDynamicSharedMemorySize, GEMM_SMEM);

    k_zero<<<(N_NODES + 255) / 256, 256>>>();
    k_wnorm<<<16, 256>>>(W);
    k_hist<<<(N_EDGES + 255) / 256, 256>>>(dst);
    k_gemm<<<(N_NODES + 127) / 128, 256, GEMM_SMEM>>>(x, W);
    k_scalars<<<1, 256>>>(a);
    {
        long long thr = (long long)N_NODES * 32;
        k_uv<<<(unsigned)((thr + 255) / 256), 256>>>();
    }
    k_sumsq<<<(N_EDGES + 255) / 256, 256>>>(src, dst);
    {
        long long thr = (long long)N_NODES * 32;
        k_final<<<(unsigned)((thr + 255) / 256), 256>>>(src, dst, out);
    }
    (void)out_size;
}

// round 4
// speedup vs baseline: 1.5054x; 1.4220x over previous
#include <cuda_runtime.h>
#include <cuda_bf16.h>
#include <math.h>
#include <cstdint>

#define N_NODES 100000
#define F_DIM   128
#define DEG     5
#define N_EDGES (N_NODES * DEG)
#define MIN_NORM 1e-15f
#define MAXNORM  0.996f

// ---------------- scratch ----------------------------------------------------
__device__ __align__(16) float g_mxT[(size_t)N_NODES * F_DIM];
__device__ __align__(16) float g_u[N_NODES];
__device__ __align__(16) float g_v[N_NODES];
__device__ int   g_cnt[N_NODES];
__device__ __align__(16) float g_msq[F_DIM];
__device__ __align__(16) float g_wsq[F_DIM];
__device__ __align__(16) float g_xs2[F_DIM];
__device__ __align__(16) float g_alpha[F_DIM];
__device__ __align__(16) float g_c1[F_DIM];
__device__ __align__(16) float g_c2[F_DIM];
__device__ float g_sumsqE;
__device__ float g_anorm;

// ---------------- math helpers ------------------------------------------------
__device__ __forceinline__ float clip1(float x) {
    return fminf(fmaxf(x, -1.0f + 1e-7f), 1.0f - 1e-7f);
}
__device__ __forceinline__ float artanh_c(float x) { return atanhf(clip1(x)); }
__device__ __forceinline__ float proj_logmap0_factor(float s, float mn) {
    float r  = fabsf(s) * mn;
    float pf = (r > MAXNORM) ? (MAXNORM / r) : 1.0f;
    float pn = fmaxf(r * pf, MIN_NORM);
    return s * pf * artanh_c(pn) / pn;
}
__device__ __forceinline__ float expmap0_proj_factor(float un) {
    un = fmaxf(un, MIN_NORM);
    float g  = tanhf(un) / un;
    float r  = fabsf(g) * un;
    float pf = (r > MAXNORM) ? (MAXNORM / r) : 1.0f;
    return g * pf;
}

__device__ __forceinline__ uint32_t smem_u32(const void* p) {
    uint32_t a;
    asm("{ .reg .u64 t; cvta.to.shared.u64 t, %1; cvt.u32.u64 %0, t; }" : "=r"(a) : "l"(p));
    return a;
}

#define CVTPK(r, f0, f1) asm("cvt.rn.bf16x2.f32 %0, %1, %2;" : "=r"(r) : "f"(f1), "f"(f0))

#define LDSM_X4(r0, r1, r2, r3, addr)                                            \
    asm volatile("ldmatrix.sync.aligned.m8n8.x4.shared.b16 {%0,%1,%2,%3}, [%4];" \
        : "=r"(r0), "=r"(r1), "=r"(r2), "=r"(r3) : "r"(addr))

#define MMA_BF16(cp, a0, a1, a2, a3, b0, b1)                                     \
    asm volatile("mma.sync.aligned.m16n8k16.row.col.f32.bf16.bf16.f32 "          \
        "{%0,%1,%2,%3}, {%4,%5,%6,%7}, {%8,%9}, {%0,%1,%2,%3};"                  \
        : "+f"((cp)[0]), "+f"((cp)[1]), "+f"((cp)[2]), "+f"((cp)[3])             \
        : "r"(a0), "r"(a1), "r"(a2), "r"(a3), "r"(b0), "r"(b1))

// ---------------- small kernels ------------------------------------------------
__global__ void k_zero() {
    int i = blockIdx.x * blockDim.x + threadIdx.x;
    if (i < N_NODES) g_cnt[i] = 0;
    if (i < F_DIM) { g_msq[i] = 0.0f; g_wsq[i] = 0.0f; }
    if (i == 0) g_sumsqE = 0.0f;
}
__global__ void k_hist(const int* __restrict__ dst) {
    int e = blockIdx.x * blockDim.x + threadIdx.x;
    if (e < N_EDGES) atomicAdd(&g_cnt[dst[e]], 1);
}
__global__ void k_wnorm(const float* __restrict__ W) {
    int w    = (blockIdx.x * blockDim.x + threadIdx.x) >> 5;
    int lane = threadIdx.x & 31;
    if (w >= F_DIM) return;
    float4 v = *(const float4*)&W[w * 128 + lane * 4];
    float s = v.x * v.x + v.y * v.y + v.z * v.z + v.w * v.w;
#pragma unroll
    for (int o = 16; o > 0; o >>= 1) s += __shfl_xor_sync(0xffffffffu, s, o);
    if (lane == 0) g_xs2[w] = s;
}

// ---------------- K1: mma.sync bf16 3-split GEMM ------------------------------
// smem: A_hi, A_lo, B_hi, B_lo tiles of [128][136] bf16 (272B row stride),
// plus per-warp reduction area red[16][128] floats.
#define ROWB   272                      // bytes per padded row (136 bf16)
#define TILEB  (128 * ROWB)             // 34816
#define SM_AH  0
#define SM_AL  (SM_AH + TILEB)
#define SM_BH  (SM_AL + TILEB)
#define SM_BL  (SM_BH + TILEB)
#define SM_RED (SM_BL + TILEB)
#define SM_TOT (SM_RED + 16 * 128 * 4)  // 147456

// convert 8 fp32 -> bf16 hi (rn) + bf16 lo (residual), store 16B each
__device__ __forceinline__ void conv8(char* smem, uint32_t hi_base, uint32_t lo_base,
                                      uint32_t off, float4 a, float4 b) {
    uint32_t p0, p1, p2, p3, q0, q1, q2, q3;
    CVTPK(p0, a.x, a.y); CVTPK(p1, a.z, a.w);
    CVTPK(p2, b.x, b.y); CVTPK(p3, b.z, b.w);
    float l0 = a.x - __uint_as_float(p0 << 16);
    float l1 = a.y - __uint_as_float(p0 & 0xffff0000u);
    float l2 = a.z - __uint_as_float(p1 << 16);
    float l3 = a.w - __uint_as_float(p1 & 0xffff0000u);
    float l4 = b.x - __uint_as_float(p2 << 16);
    float l5 = b.y - __uint_as_float(p2 & 0xffff0000u);
    float l6 = b.z - __uint_as_float(p3 << 16);
    float l7 = b.w - __uint_as_float(p3 & 0xffff0000u);
    CVTPK(q0, l0, l1); CVTPK(q1, l2, l3); CVTPK(q2, l4, l5); CVTPK(q3, l6, l7);
    *(uint4*)(smem + hi_base + off) = make_uint4(p0, p1, p2, p3);
    *(uint4*)(smem + lo_base + off) = make_uint4(q0, q1, q2, q3);
}

__device__ __forceinline__ void mma_pass(uint32_t a_base, uint32_t b_base, float c[8][4]) {
#pragma unroll
    for (int ks = 0; ks < 8; ks++) {
        uint32_t a0, a1, a2, a3;
        LDSM_X4(a0, a1, a2, a3, a_base + ks * 32);
#pragma unroll
        for (int jj = 0; jj < 4; jj++) {
            uint32_t b0, b1, b2, b3;
            LDSM_X4(b0, b1, b2, b3, b_base + jj * (16 * ROWB) + ks * 32);
            MMA_BF16(c[2 * jj],     a0, a1, a2, a3, b0, b1);
            MMA_BF16(c[2 * jj + 1], a0, a1, a2, a3, b2, b3);
        }
    }
}

__global__ __launch_bounds__(512, 1) void k_gemm_mma(const float* __restrict__ x,
                                                     const float* __restrict__ W) {
    extern __shared__ __align__(1024) char smem[];
    const uint32_t sbase = smem_u32(smem);
    const int tid  = threadIdx.x;
    const int wid  = tid >> 5;
    const int lane = tid & 31;
    const int base = blockIdx.x * 128;

    float* red = (float*)(smem + SM_RED);
    for (int i = tid; i < 16 * 128; i += 512) red[i] = 0.0f;

    // --- stage + split-convert A (x tile) and B (W) -----------------------------
#pragma unroll
    for (int it = 0; it < 4; it++) {                // A: 128 rows x 16 groups
        int i = tid + it * 512;
        int row = i >> 4, g = i & 15;
        int grow = base + row;
        float4 a = make_float4(0.f, 0.f, 0.f, 0.f), b = a;
        if (grow < N_NODES) {
            const float* p = &x[(size_t)grow * 128 + g * 8];
            a = *(const float4*)p;
            b = *(const float4*)(p + 4);
        }
        conv8(smem, SM_AH, SM_AL, (uint32_t)row * ROWB + g * 16, a, b);
    }
#pragma unroll
    for (int it = 0; it < 4; it++) {                // B: W[f][k]
        int i = tid + it * 512;
        int row = i >> 4, g = i & 15;
        const float* p = &W[row * 128 + g * 8];
        float4 a = *(const float4*)p;
        float4 b = *(const float4*)(p + 4);
        conv8(smem, SM_BH, SM_BL, (uint32_t)row * ROWB + g * 16, a, b);
    }
    __syncthreads();

    // --- warp tiles: wm rows (16), wn col-half (64) -----------------------------
    const int wm = wid & 7, wn = wid >> 3;
    const int wbase = wm * 16, nbase = wn * 64;

    // ldmatrix per-lane addresses
    uint32_t a_off = (uint32_t)(wbase + (lane & 15)) * ROWB + ((lane >> 4) ? 16u : 0u);
    uint32_t b_row = (uint32_t)(nbase + ((lane >> 4) << 3) + (lane & 7));
    uint32_t b_off = b_row * ROWB + (((lane >> 3) & 1) ? 16u : 0u);

    float c[8][4];
#pragma unroll
    for (int i = 0; i < 8; i++)
#pragma unroll
        for (int j = 0; j < 4; j++) c[i][j] = 0.0f;

    mma_pass(sbase + SM_AH + a_off, sbase + SM_BH + b_off, c);   // hi*hi
    mma_pass(sbase + SM_AH + a_off, sbase + SM_BL + b_off, c);   // hi*lo
    mma_pass(sbase + SM_AL + a_off, sbase + SM_BH + b_off, c);   // lo*hi

    // --- epilogue: store mxT + per-feature column sums ---------------------------
    int lr0 = wbase + (lane >> 2);
    int grow0 = base + lr0, grow1 = grow0 + 8;
    bool v0 = grow0 < N_NODES, v1 = grow1 < N_NODES;
    float cf0 = v0 ? (float)g_cnt[grow0] : 0.0f;
    float cf1 = v1 ? (float)g_cnt[grow1] : 0.0f;
    float* redw = red + wid * 128;    // [0:64) ssq, [64:128) wsq for this warp's cols

#pragma unroll
    for (int nt = 0; nt < 8; nt++) {
        int col = nbase + nt * 8 + (lane & 3) * 2;
        if (v0) *(float2*)&g_mxT[(size_t)grow0 * 128 + col] = make_float2(c[nt][0], c[nt][1]);
        if (v1) *(float2*)&g_mxT[(size_t)grow1 * 128 + col] = make_float2(c[nt][2], c[nt][3]);
        float q0 = c[nt][0] * c[nt][0], q1 = c[nt][1] * c[nt][1];
        float q2 = c[nt][2] * c[nt][2], q3 = c[nt][3] * c[nt][3];
        float s0 = q0 + q2,             s1 = q1 + q3;
        float w0 = cf0 * q0 + cf1 * q2, w1 = cf0 * q1 + cf1 * q3;
#pragma unroll
        for (int o = 4; o <= 16; o <<= 1) {
            s0 += __shfl_xor_sync(0xffffffffu, s0, o);
            s1 += __shfl_xor_sync(0xffffffffu, s1, o);
            w0 += __shfl_xor_sync(0xffffffffu, w0, o);
            w1 += __shfl_xor_sync(0xffffffffu, w1, o);
        }
        if (lane < 4) {
            int lc = nt * 8 + lane * 2;
            redw[lc]          += s0;
            redw[lc + 1]      += s1;
            redw[64 + lc]     += w0;
            redw[64 + lc + 1] += w1;
        }
    }
    __syncthreads();

    // cross-warp reduce + one global atomic per column per array
    if (tid < 256) {
        int col = tid & 127, arr = tid >> 7;
        int wnc = col >> 6, lc = (col & 63) + arr * 64;
        float s = 0.0f;
#pragma unroll
        for (int wmc = 0; wmc < 8; wmc++) s += red[(wnc * 8 + wmc) * 128 + lc];
        atomicAdd(arr ? &g_wsq[col] : &g_msq[col], s);
    }
}

// ---------------- K2: per-feature scalar chain --------------------------------
__global__ __launch_bounds__(256) void k_scalars(const float* __restrict__ a) {
    __shared__ float sred[256];
    int tid = threadIdx.x;
    float av = a[tid];
    sred[tid] = av * av;
    __syncthreads();
    for (int s = 128; s > 0; s >>= 1) {
        if (tid < s) sred[tid] += sred[tid + s];
        __syncthreads();
    }
    float an = fmaxf(sqrtf(sred[0]), MIN_NORM);
    if (tid == 0) g_anorm = an;

    if (tid < 128) {
        int f = tid;
        float xn = fmaxf(sqrtf(g_xs2[f]), MIN_NORM);
        float mn = fmaxf(sqrtf(g_msq[f]), MIN_NORM);
        float s1 = tanhf(mn / xn * artanh_c(xn)) / mn;
        float alpha = proj_logmap0_factor(s1, mn);
        g_alpha[f] = alpha;
        float un_s = fabsf(alpha) * sqrtf(5.0f * g_msq[f]);
        float un_d = fabsf(alpha) * sqrtf(g_wsq[f]);
        g_c1[f] = a[f]       * expmap0_proj_factor(un_s) * alpha;
        g_c2[f] = a[128 + f] * expmap0_proj_factor(un_d) * alpha;
    }
}

// ---------------- K3: per-node dots -------------------------------------------
__global__ void k_uv() {
    int gw   = (blockIdx.x * blockDim.x + threadIdx.x) >> 5;
    int lane = threadIdx.x & 31;
    if (gw >= N_NODES) return;
    float4 c1 = *(const float4*)&g_c1[lane * 4];
    float4 c2 = *(const float4*)&g_c2[lane * 4];
    float4 m  = *(const float4*)&g_mxT[(size_t)gw * 128 + lane * 4];
    float du = m.x * c1.x + m.y * c1.y + m.z * c1.z + m.w * c1.w;
    float dv = m.x * c2.x + m.y * c2.y + m.z * c2.z + m.w * c2.w;
#pragma unroll
    for (int o = 16; o > 0; o >>= 1) {
        du += __shfl_xor_sync(0xffffffffu, du, o);
        dv += __shfl_xor_sync(0xffffffffu, dv, o);
    }
    if (lane == 0) { g_u[gw] = du; g_v[gw] = dv; }
}

// ---------------- K4: sum of squares of edge logits ---------------------------
__global__ void k_sumsq(const int* __restrict__ src, const int* __restrict__ dst) {
    __shared__ float sb[256];
    int e = blockIdx.x * blockDim.x + threadIdx.x;
    float sq = 0.0f;
    if (e < N_EDGES) {
        float m = g_u[src[e]] + g_v[dst[e]];
        sq = m * m;
    }
    sb[threadIdx.x] = sq;
    __syncthreads();
    for (int s = 128; s > 0; s >>= 1) {
        if (threadIdx.x < s) sb[threadIdx.x] += sb[threadIdx.x + s];
        __syncthreads();
    }
    if (threadIdx.x == 0) atomicAdd(&g_sumsqE, sb[0]);
}

// ---------------- K5: final aggregation ----------------------------------------
__device__ __forceinline__ float compute_gamma() {
    float mn = fmaxf(sqrtf(g_sumsqE), MIN_NORM);
    float an = g_anorm;
    float s2 = tanhf(mn / an * artanh_c(an)) / mn;
    return proj_logmap0_factor(s2, mn);
}

__global__ __launch_bounds__(256) void k_final(const int* __restrict__ src,
                                               const int* __restrict__ dst,
                                               float* __restrict__ out) {
    int n    = (blockIdx.x * blockDim.x + threadIdx.x) >> 5;
    int lane = threadIdx.x & 31;
    if (n >= N_NODES) return;
    float gamma = compute_gamma();

    float wj = 0.0f;
    int   dj = 0;
    if (lane < DEG) {
        int e = n * DEG + lane;
        int s = src[e];
        dj = dst[e];
        float mxE = g_u[s] + g_v[dj];
        float ee  = gamma * mxE;
        float ge  = 0.5f * ee * (1.0f + erff(ee * 0.70710678118654752f));
        wj = expf(-ge);
    }

    float4 acc = make_float4(0.f, 0.f, 0.f, 0.f);
    float wsum = 0.0f;
#pragma unroll
    for (int j = 0; j < DEG; j++) {
        float w = __shfl_sync(0xffffffffu, wj, j);
        int   d = __shfl_sync(0xffffffffu, dj, j);
        float4 m = *(const float4*)&g_mxT[(size_t)d * 128 + lane * 4];
        acc.x += w * m.x; acc.y += w * m.y; acc.z += w * m.z; acc.w += w * m.w;
        wsum += w;
    }
    float4 al  = *(const float4*)&g_alpha[lane * 4];
    float  inv = 1.0f / wsum;
    float4 hp = make_float4(acc.x * al.x * inv, acc.y * al.y * inv,
                            acc.z * al.z * inv, acc.w * al.w * inv);
    float4 e4;
    e4.x = (hp.x > 0.f) ? hp.x : expm1f(hp.x);
    e4.y = (hp.y > 0.f) ? hp.y : expm1f(hp.y);
    e4.z = (hp.z > 0.f) ? hp.z : expm1f(hp.z);
    e4.w = (hp.w > 0.f) ? hp.w : expm1f(hp.w);
    float ssq = e4.x * e4.x + e4.y * e4.y + e4.z * e4.z + e4.w * e4.w;
#pragma unroll
    for (int o = 16; o > 0; o >>= 1) ssq += __shfl_xor_sync(0xffffffffu, ssq, o);
    float un  = fmaxf(sqrtf(ssq), MIN_NORM);
    float fac = expmap0_proj_factor(un);
    float4 o4 = make_float4(e4.x * fac, e4.y * fac, e4.z * fac, e4.w * fac);
    *(float4*)&out[(size_t)n * 128 + lane * 4] = o4;
}

// ---------------- launch --------------------------------------------------------
extern "C" void kernel_launch(void* const* d_in, const int* in_sizes, int n_in,
                              void* d_out, int out_size) {
    const float* x = nullptr;
    const float* W = nullptr;
    const float* a = nullptr;
    const int* edge = nullptr;
    for (int i = 0; i < n_in; i++) {
        switch (in_sizes[i]) {
            case N_NODES * F_DIM: x    = (const float*)d_in[i]; break;
            case 2 * N_EDGES:     edge = (const int*)d_in[i];   break;
            case F_DIM * F_DIM:   W    = (const float*)d_in[i]; break;
            case 2 * F_DIM:       a    = (const float*)d_in[i]; break;
            default: break;
        }
    }
    const int* src = edge;
    const int* dst = edge + N_EDGES;
    float* out = (float*)d_out;

    cudaFuncSetAttribute(k_gemm_mma, cudaFuncAttributeMaxDynamicSharedMemorySize, SM_TOT);

    k_zero<<<(N_NODES + 255) / 256, 256>>>();
    k_wnorm<<<16, 256>>>(W);
    k_hist<<<(N_EDGES + 255) / 256, 256>>>(dst);
    k_gemm_mma<<<(N_NODES + 127) / 128, 512, SM_TOT>>>(x, W);
    k_scalars<<<1, 256>>>(a);
    {
        long long thr = (long long)N_NODES * 32;
        k_uv<<<(unsigned)((thr + 255) / 256), 256>>>();
    }
    k_sumsq<<<(N_EDGES + 255) / 256, 256>>>(src, dst);
    {
        long long thr = (long long)N_NODES * 32;
        k_final<<<(unsigned)((thr + 255) / 256), 256>>>(src, dst, out);
    }
    (void)out_size;
}